// round 11
// baseline (speedup 1.0000x reference)
#include <cuda_runtime.h>
#include <cstdint>
#include <cstddef>

// Problem constants
#define B_   32
#define S_   1024
#define I_   1024
#define H_   1024
#define IH_  2048
#define K3_  3072
#define GRID2 128   // persistent CTAs for recurrent phase (1 CTA/SM, all co-resident)
#define NH_  8      // h-columns per CTA (128*8 = 1024)
#define NC_  24     // gate columns per CTA (3 gates * 8)
#define GPAD 33     // padded stride for gate[] (bank-conflict-free epilogue)

// Scratch (static device allocations are the sanctioned scratch mechanism)
__device__ float    g_Gx[(size_t)B_ * S_ * K3_];  // [s][b][col], col = g*1024 + j, bias folded in
__device__ float    g_hT[2][H_ * B_];             // h transposed [k][b], double-buffered per step
__device__ unsigned g_bar;                        // grid barrier counter (reset each launch)

// ---- packed f32x2 helpers (2x FFMA throughput on sm_103a) ----
static __device__ __forceinline__ unsigned long long pk2(float lo, float hi) {
    unsigned long long r;
    asm("mov.b64 %0, {%1, %2};" : "=l"(r) : "f"(lo), "f"(hi));
    return r;
}
static __device__ __forceinline__ float2 up2(unsigned long long v) {
    float2 f;
    asm("mov.b64 {%0, %1}, %2;" : "=f"(f.x), "=f"(f.y) : "l"(v));
    return f;
}
static __device__ __forceinline__ unsigned long long ffma2(
    unsigned long long a, unsigned long long b, unsigned long long c) {
    unsigned long long d;
    asm("fma.rn.f32x2 %0, %1, %2, %3;" : "=l"(d) : "l"(a), "l"(b), "l"(c));
    return d;
}

// ============================================================================
// Kernel 1: Gx = X2d @ Wx^T + bias     (X2d rows r = b*S + s, x is contiguous)
// Tiles: BM=128 rows, BN=128 cols, BK=16. 256 threads, 8x8 thread tile, f32x2.
// Output layout: g_Gx[(s*32 + b)*3072 + g*1024 + j]
// ALSO (fused init, bx==0 blocks): transpose h0 into g_hT[0], reset g_bar.
// Stream ordering guarantees this completes before lstm_kernel launches.
// ============================================================================
__global__ __launch_bounds__(256) void xw_kernel(
    const float* __restrict__ x,  const float* __restrict__ h0,
    const float* __restrict__ Wf, const float* __restrict__ bf,
    const float* __restrict__ Wo, const float* __restrict__ bo,
    const float* __restrict__ Wc, const float* __restrict__ bc)
{
    __shared__ float As[16 * 132];   // [k][r], padded stride 132 (16B-multiple)
    __shared__ float Bs[16 * 132];   // [k][c]

    const int tid  = threadIdx.x;
    const int bx   = blockIdx.x;      // 0..23  (col tile; 8 tiles per gate)
    const int by   = blockIdx.y;      // 0..255 (row tile)

    // ---- fused init: 256 bx==0 blocks x 128 threads = 32768 transposes ----
    if (bx == 0) {
        if (tid < 128) {
            int idx = by * 128 + tid;    // 0..32767
            int k = idx >> 5;
            int b = idx & 31;
            g_hT[0][k * B_ + b] = h0[b * H_ + k];
        }
        if (by == 0 && tid == 255) g_bar = 0u;
    }

    const int g    = bx >> 3;
    const float* W    = (g == 0) ? Wf : (g == 1) ? Wo : Wc;
    const float* bias = (g == 0) ? bf : (g == 1) ? bo : bc;
    const int jb   = (bx & 7) * 128;  // j offset within gate
    const int row0 = by * 128;
    const int tx   = tid & 15;        // col group (8 cols)
    const int ty   = tid >> 4;        // row group (8 rows)

    unsigned long long acc[8][4];
#pragma unroll
    for (int i = 0; i < 8; i++)
#pragma unroll
        for (int j = 0; j < 4; j++) acc[i][j] = pk2(0.f, 0.f);

    for (int k0 = 0; k0 < I_; k0 += 16) {
#pragma unroll
        for (int it = 0; it < 2; it++) {
            int i = tid + it * 256;   // 0..511
            int r = i >> 2;           // 0..127
            int q = i & 3;            // which float4 along k
            float4 av = *(const float4*)(x + (size_t)(row0 + r) * I_ + k0 + q * 4);
            As[(q * 4 + 0) * 132 + r] = av.x;
            As[(q * 4 + 1) * 132 + r] = av.y;
            As[(q * 4 + 2) * 132 + r] = av.z;
            As[(q * 4 + 3) * 132 + r] = av.w;
            float4 bv = *(const float4*)(W + (size_t)(jb + r) * IH_ + k0 + q * 4);
            Bs[(q * 4 + 0) * 132 + r] = bv.x;
            Bs[(q * 4 + 1) * 132 + r] = bv.y;
            Bs[(q * 4 + 2) * 132 + r] = bv.z;
            Bs[(q * 4 + 3) * 132 + r] = bv.w;
        }
        __syncthreads();

#pragma unroll
        for (int kk = 0; kk < 16; kk++) {
            float4 a0 = *(const float4*)&As[kk * 132 + ty * 8];
            float4 a1 = *(const float4*)&As[kk * 132 + ty * 8 + 4];
            const unsigned long long* bp =
                (const unsigned long long*)&Bs[kk * 132 + tx * 8];
            unsigned long long b2[4];
            b2[0] = bp[0]; b2[1] = bp[1]; b2[2] = bp[2]; b2[3] = bp[3];
            unsigned long long aa[8];
            aa[0] = pk2(a0.x, a0.x); aa[1] = pk2(a0.y, a0.y);
            aa[2] = pk2(a0.z, a0.z); aa[3] = pk2(a0.w, a0.w);
            aa[4] = pk2(a1.x, a1.x); aa[5] = pk2(a1.y, a1.y);
            aa[6] = pk2(a1.z, a1.z); aa[7] = pk2(a1.w, a1.w);
#pragma unroll
            for (int i = 0; i < 8; i++)
#pragma unroll
                for (int j = 0; j < 4; j++)
                    acc[i][j] = ffma2(aa[i], b2[j], acc[i][j]);
        }
        __syncthreads();
    }

    // epilogue: add bias, scatter to [(s*32 + b)*3072 + g*1024 + jb + c]
    float bvv[8];
#pragma unroll
    for (int j = 0; j < 8; j++) bvv[j] = bias[jb + tx * 8 + j];

#pragma unroll
    for (int ry = 0; ry < 8; ry++) {
        int r = row0 + ty * 8 + ry;
        int b = r >> 10;
        int s = r & 1023;
        float* dst = g_Gx + (size_t)((s << 5) + b) * K3_ + g * 1024 + jb + tx * 8;
#pragma unroll
        for (int j = 0; j < 4; j++) {
            float2 v = up2(acc[ry][j]);
            v.x += bvv[j * 2];
            v.y += bvv[j * 2 + 1];
            *(float2*)(dst + j * 2) = v;
        }
    }
}

// ============================================================================
// Kernel 2: persistent recurrent loop (R7 configuration + pipelined staging).
// 128 CTAs, each owns NH_=8 h-indices -> 24 gate columns. Wh slice (96 KB)
// lives in SMEM for all 1024 steps; cell state lives in a register. h is
// staged per 256-k chunk; the NEXT chunk's global loads are prefetched into
// registers under the current chunk's GEMM. Nanosleep grid barrier (R7's —
// the only barrier variant that measured well).
// ============================================================================
__global__ __launch_bounds__(256) void lstm_kernel(
    const float* __restrict__ Wf, const float* __restrict__ Wo,
    const float* __restrict__ Wc, const float* __restrict__ c0,
    float* __restrict__ out)
{
    extern __shared__ float sm[];
    float* ws   = sm;                 // [1024][24]  Wh slice (fp32)  = 24576 floats
    float* hs   = sm + 24576;         // [256][32]   staged h chunk   =  8192 floats
    float* gate = hs + 8192;          // [24][GPAD]  partial-sum accumulators = 792

    const int tid   = threadIdx.x;
    const int jbase = blockIdx.x * NH_;
    const int lane  = tid & 31;
    const int tk    = tid >> 5;     // 8 k-groups (one per warp)
    const int tp    = lane & 7;     // 8 b-groups (4 b's each)
    const int tc    = lane >> 3;    // 4 col groups (6 cols each)

    // ---- one-time: load Wh slice into SMEM (cols ordered f(8), o(8), c(8)) ----
    for (int cl = 0; cl < NC_; cl++) {
        int gg = cl >> 3, jl2 = cl & 7;
        const float* W = (gg == 0) ? Wf : (gg == 1) ? Wo : Wc;
        const float* wrow = W + (size_t)(jbase + jl2) * IH_ + I_;   // h-part columns
        for (int k = tid; k < H_; k += 256) ws[k * NC_ + cl] = wrow[k];
    }

    // epilogue mapping: b fastest-varying across jl for coalesced Gx reads
    const int bb = tid >> 3;         // batch 0..31
    const int jl = tid & 7;          // local h-index 0..7

    // ---- cell state lives in a register for the whole sequence ----
    float creg = c0[(size_t)bb * H_ + jbase + jl];
    __syncthreads();

    for (int t = 0; t < S_; t++) {
        // prefetch this step's Gx values (consumed ~6K cycles later in epilogue)
        const float* gx = g_Gx + (size_t)(t * 32 + bb) * K3_ + jbase + jl;
        float gxf = __ldg(gx);
        float gxo = __ldg(gx + 1024);
        float gxc = __ldg(gx + 2048);

        // zero gate accumulators (24 * GPAD = 792)
        for (int i = tid; i < NC_ * GPAD; i += 256) gate[i] = 0.f;

        unsigned long long acc[4][3];
#pragma unroll
        for (int i = 0; i < 4; i++)
#pragma unroll
            for (int j = 0; j < 3; j++) acc[i][j] = pk2(0.f, 0.f);

        const float* hsrc = g_hT[t & 1];

        // prologue: prefetch chunk 0 (256 k-rows = 8192 floats) into registers
        float4 r[8];
#pragma unroll
        for (int i = 0; i < 8; i++)
            r[i] = ((const float4*)hsrc)[tid + i * 256];

        for (int ch = 0; ch < 4; ch++) {
            __syncthreads();   // prev chunk's hs reads done; gate zero visible
            // store staged registers -> hs (plain copy, same layout as R7)
            float4* dst4 = (float4*)hs;
#pragma unroll
            for (int i = 0; i < 8; i++) dst4[tid + i * 256] = r[i];
            __syncthreads();

            // prefetch next chunk (LDG latency hides under this chunk's GEMM)
            if (ch < 3) {
                const float4* nsrc = (const float4*)(hsrc + (ch + 1) * 8192);
#pragma unroll
                for (int i = 0; i < 8; i++)
                    r[i] = nsrc[tid + i * 256];
            }

            // GEMM over this chunk's 256 k (k-split 8 ways across warps)
            const int kg0 = ch * 256 + tk * 32;
#pragma unroll 4
            for (int kk = 0; kk < 32; kk++) {
                int kloc = tk * 32 + kk;
                float4 av = *(const float4*)&hs[kloc * 32 + tp * 4];
                unsigned long long aa[4];
                aa[0] = pk2(av.x, av.x); aa[1] = pk2(av.y, av.y);
                aa[2] = pk2(av.z, av.z); aa[3] = pk2(av.w, av.w);
                const unsigned long long* wp =
                    (const unsigned long long*)&ws[(kg0 + kk) * NC_ + tc * 6];
                unsigned long long w0 = wp[0], w1 = wp[1], w2 = wp[2];
#pragma unroll
                for (int i = 0; i < 4; i++) {
                    acc[i][0] = ffma2(aa[i], w0, acc[i][0]);
                    acc[i][1] = ffma2(aa[i], w1, acc[i][1]);
                    acc[i][2] = ffma2(aa[i], w2, acc[i][2]);
                }
            }
        }
        __syncthreads();

        // reduce 8-way k-split partials into gate[cl][b]
#pragma unroll
        for (int i = 0; i < 4; i++) {
            int b = tp * 4 + i;
#pragma unroll
            for (int j = 0; j < 3; j++) {
                float2 v = up2(acc[i][j]);
                int cl = tc * 6 + j * 2;
                atomicAdd(&gate[cl * GPAD + b], v.x);
                atomicAdd(&gate[(cl + 1) * GPAD + b], v.y);
            }
        }
        __syncthreads();

        // ---- epilogue: gates -> cell update -> h ----
        {
            float sf = gate[jl * GPAD + bb]        + gxf;
            float so = gate[(8 + jl) * GPAD + bb]  + gxo;
            float sc = gate[(16 + jl) * GPAD + bb] + gxc;
            float f    = 1.f / (1.f + expf(-sf));
            float o    = 1.f / (1.f + expf(-so));
            float chat = tanhf(sc);
            float cn   = f * creg + (1.f - f) * chat;
            float hn   = o * tanhf(cn);
            creg = cn;
            out[(size_t)(bb * S_ + t) * H_ + jbase + jl] = hn;
            g_hT[1 - (t & 1)][(jbase + jl) * 32 + bb] = hn;
            if (t == S_ - 1) {
                out[(size_t)B_ * S_ * H_ + (size_t)bb * H_ + jbase + jl] = hn;  // h_T
                out[(size_t)B_ * S_ * H_ + (size_t)B_ * H_
                    + (size_t)bb * H_ + jbase + jl] = cn;                        // c_T
            }
        }

        // ---- grid barrier (R7: release fence+atomic; acquire nanosleep-poll) ----
        __threadfence();
        __syncthreads();
        if (tid == 0) {
            atomicAdd(&g_bar, 1u);
            unsigned target = (unsigned)GRID2 * (unsigned)(t + 1);
            while (*((volatile unsigned*)&g_bar) < target) __nanosleep(64);
            __threadfence();
        }
        __syncthreads();
    }
}

// ============================================================================
// Host launcher
// ============================================================================
extern "C" void kernel_launch(void* const* d_in, const int* in_sizes, int n_in,
                              void* d_out, int out_size) {
    (void)in_sizes; (void)n_in; (void)out_size;
    const float* x  = (const float*)d_in[0];
    const float* h0 = (const float*)d_in[1];
    const float* c0 = (const float*)d_in[2];
    const float* Wf = (const float*)d_in[3];
    const float* bf = (const float*)d_in[4];
    const float* Wo = (const float*)d_in[5];
    const float* bo = (const float*)d_in[6];
    const float* Wc = (const float*)d_in[7];
    const float* bc = (const float*)d_in[8];
    float* out = (float*)d_out;

    // 134240 B dynamic SMEM for the persistent kernel -> occupancy 1 CTA/SM,
    // grid 128 <= SM count, so all CTAs are co-resident (grid barrier is safe).
    const int kSmem = (24576 + 8192 + NC_ * GPAD) * 4;
    cudaFuncSetAttribute(lstm_kernel, cudaFuncAttributeMaxDynamicSharedMemorySize,
                         kSmem);

    dim3 g1(24, 256);
    xw_kernel<<<g1, 256>>>(x, h0, Wf, bf, Wo, bo, Wc, bc);

    lstm_kernel<<<GRID2, 256, kSmem>>>(Wf, Wo, Wc, c0, out);
}

// round 15
// speedup vs baseline: 1.8187x; 1.8187x over previous
#include <cuda_runtime.h>
#include <cstdint>
#include <cstddef>

// Problem constants
#define B_   32
#define S_   1024
#define I_   1024
#define H_   1024
#define IH_  2048
#define K3_  3072
#define GRID2 128   // persistent CTAs for recurrent phase (1 CTA/SM, all co-resident)
#define NH_  8      // h-columns per CTA (128*8 = 1024)
#define NC_  24     // gate columns per CTA (3 gates * 8)
#define GPAD 33     // padded stride for gate[] (bank-conflict-free epilogue)

// Scratch (static device allocations are the sanctioned scratch mechanism)
__device__ float    g_Gx[(size_t)B_ * S_ * K3_];  // [s][b][col], col = g*1024 + j, bias folded in
__device__ float    g_hT[2][H_ * B_];             // h transposed [k][b], double-buffered per step
__device__ unsigned g_bar;                        // grid barrier counter (reset each launch)

// ---- packed f32x2 helpers (2x FFMA throughput on sm_103a) ----
static __device__ __forceinline__ unsigned long long pk2(float lo, float hi) {
    unsigned long long r;
    asm("mov.b64 %0, {%1, %2};" : "=l"(r) : "f"(lo), "f"(hi));
    return r;
}
static __device__ __forceinline__ float2 up2(unsigned long long v) {
    float2 f;
    asm("mov.b64 {%0, %1}, %2;" : "=f"(f.x), "=f"(f.y) : "l"(v));
    return f;
}
static __device__ __forceinline__ unsigned long long ffma2(
    unsigned long long a, unsigned long long b, unsigned long long c) {
    unsigned long long d;
    asm("fma.rn.f32x2 %0, %1, %2, %3;" : "=l"(d) : "l"(a), "l"(b), "l"(c));
    return d;
}

// ============================================================================
// Kernel 1: Gx = X2d @ Wx^T + bias     (X2d rows r = b*S + s, x is contiguous)
// Tiles: BM=128 rows, BN=128 cols, BK=16. 256 threads, 8x8 thread tile, f32x2.
// Output layout: g_Gx[(s*32 + b)*3072 + g*1024 + j]
// ALSO (fused init, bx==0 blocks): transpose h0 into g_hT[0], reset g_bar.
// Stream ordering guarantees this completes before lstm_kernel launches.
// ============================================================================
__global__ __launch_bounds__(256) void xw_kernel(
    const float* __restrict__ x,  const float* __restrict__ h0,
    const float* __restrict__ Wf, const float* __restrict__ bf,
    const float* __restrict__ Wo, const float* __restrict__ bo,
    const float* __restrict__ Wc, const float* __restrict__ bc)
{
    __shared__ float As[16 * 132];   // [k][r], padded stride 132 (16B-multiple)
    __shared__ float Bs[16 * 132];   // [k][c]

    const int tid  = threadIdx.x;
    const int bx   = blockIdx.x;      // 0..23  (col tile; 8 tiles per gate)
    const int by   = blockIdx.y;      // 0..255 (row tile)

    // ---- fused init: 256 bx==0 blocks x 128 threads = 32768 transposes ----
    if (bx == 0) {
        if (tid < 128) {
            int idx = by * 128 + tid;    // 0..32767
            int k = idx >> 5;
            int b = idx & 31;
            g_hT[0][k * B_ + b] = h0[b * H_ + k];
        }
        if (by == 0 && tid == 255) g_bar = 0u;
    }

    const int g    = bx >> 3;
    const float* W    = (g == 0) ? Wf : (g == 1) ? Wo : Wc;
    const float* bias = (g == 0) ? bf : (g == 1) ? bo : bc;
    const int jb   = (bx & 7) * 128;  // j offset within gate
    const int row0 = by * 128;
    const int tx   = tid & 15;        // col group (8 cols)
    const int ty   = tid >> 4;        // row group (8 rows)

    unsigned long long acc[8][4];
#pragma unroll
    for (int i = 0; i < 8; i++)
#pragma unroll
        for (int j = 0; j < 4; j++) acc[i][j] = pk2(0.f, 0.f);

    for (int k0 = 0; k0 < I_; k0 += 16) {
#pragma unroll
        for (int it = 0; it < 2; it++) {
            int i = tid + it * 256;   // 0..511
            int r = i >> 2;           // 0..127
            int q = i & 3;            // which float4 along k
            float4 av = *(const float4*)(x + (size_t)(row0 + r) * I_ + k0 + q * 4);
            As[(q * 4 + 0) * 132 + r] = av.x;
            As[(q * 4 + 1) * 132 + r] = av.y;
            As[(q * 4 + 2) * 132 + r] = av.z;
            As[(q * 4 + 3) * 132 + r] = av.w;
            float4 bv = *(const float4*)(W + (size_t)(jb + r) * IH_ + k0 + q * 4);
            Bs[(q * 4 + 0) * 132 + r] = bv.x;
            Bs[(q * 4 + 1) * 132 + r] = bv.y;
            Bs[(q * 4 + 2) * 132 + r] = bv.z;
            Bs[(q * 4 + 3) * 132 + r] = bv.w;
        }
        __syncthreads();

#pragma unroll
        for (int kk = 0; kk < 16; kk++) {
            float4 a0 = *(const float4*)&As[kk * 132 + ty * 8];
            float4 a1 = *(const float4*)&As[kk * 132 + ty * 8 + 4];
            const unsigned long long* bp =
                (const unsigned long long*)&Bs[kk * 132 + tx * 8];
            unsigned long long b2[4];
            b2[0] = bp[0]; b2[1] = bp[1]; b2[2] = bp[2]; b2[3] = bp[3];
            unsigned long long aa[8];
            aa[0] = pk2(a0.x, a0.x); aa[1] = pk2(a0.y, a0.y);
            aa[2] = pk2(a0.z, a0.z); aa[3] = pk2(a0.w, a0.w);
            aa[4] = pk2(a1.x, a1.x); aa[5] = pk2(a1.y, a1.y);
            aa[6] = pk2(a1.z, a1.z); aa[7] = pk2(a1.w, a1.w);
#pragma unroll
            for (int i = 0; i < 8; i++)
#pragma unroll
                for (int j = 0; j < 4; j++)
                    acc[i][j] = ffma2(aa[i], b2[j], acc[i][j]);
        }
        __syncthreads();
    }

    // epilogue: add bias, scatter to [(s*32 + b)*3072 + g*1024 + jb + c]
    float bvv[8];
#pragma unroll
    for (int j = 0; j < 8; j++) bvv[j] = bias[jb + tx * 8 + j];

#pragma unroll
    for (int ry = 0; ry < 8; ry++) {
        int r = row0 + ty * 8 + ry;
        int b = r >> 10;
        int s = r & 1023;
        float* dst = g_Gx + (size_t)((s << 5) + b) * K3_ + g * 1024 + jb + tx * 8;
#pragma unroll
        for (int j = 0; j < 4; j++) {
            float2 v = up2(acc[ry][j]);
            v.x += bvv[j * 2];
            v.y += bvv[j * 2 + 1];
            *(float2*)(dst + j * 2) = v;
        }
    }
}

// ============================================================================
// Kernel 2: persistent recurrent loop.
// 128 CTAs, each owns NH_=8 h-indices -> 24 gate columns. Wh slice (96 KB)
// lives in SMEM for all 1024 steps; cell state lives in a register.
// NEW: the ENTIRE 32 KB h vector is staged into SMEM in ONE burst per step
// (2048 LDG.128 per CTA, latency amortized once), then the GEMM runs over
// all 1024 k uninterrupted. The gate accumulator array ALIASES the h buffer
// (reused only after the last GEMM read). No prefetch registers (R9-R11's
// measured poison). R7's nanosleep grid barrier, untouched.
// SMEM: 96KB ws + 128KB hs = 229376 B <= 232448 B block limit; 1 CTA/SM.
// ============================================================================
__global__ __launch_bounds__(256) void lstm_kernel(
    const float* __restrict__ Wf, const float* __restrict__ Wo,
    const float* __restrict__ Wc, const float* __restrict__ c0,
    float* __restrict__ out)
{
    extern __shared__ float sm[];
    float* ws   = sm;                 // [1024][24]  Wh slice (fp32) = 24576 floats (96KB)
    float* hs   = sm + 24576;         // [1024][32]  full staged h   = 32768 floats (128KB)
    float* gate = hs;                 // [24][GPAD]  partials — ALIASES hs (zeroed only
                                      //  after the last GEMM read of hs)

    const int tid   = threadIdx.x;
    const int jbase = blockIdx.x * NH_;
    const int lane  = tid & 31;
    const int tk    = tid >> 5;     // 8 k-groups (one warp each, 128 k per warp)
    const int tp    = lane & 7;     // 8 b-groups (4 batches each)
    const int tc    = lane >> 3;    // 4 col groups (6 cols each)

    // ---- one-time: load Wh slice into SMEM (cols ordered f(8), o(8), c(8)) ----
    for (int cl = 0; cl < NC_; cl++) {
        int gg = cl >> 3, jl2 = cl & 7;
        const float* W = (gg == 0) ? Wf : (gg == 1) ? Wo : Wc;
        const float* wrow = W + (size_t)(jbase + jl2) * IH_ + I_;   // h-part columns
        for (int k = tid; k < H_; k += 256) ws[k * NC_ + cl] = wrow[k];
    }

    // epilogue mapping: b fastest-varying across jl for coalesced Gx reads
    const int bb = tid >> 3;         // batch 0..31
    const int jl = tid & 7;          // local h-index 0..7

    // ---- cell state lives in a register for the whole sequence ----
    float creg = c0[(size_t)bb * H_ + jbase + jl];
    __syncthreads();

    for (int t = 0; t < S_; t++) {
        // prefetch this step's Gx values (consumed in the epilogue)
        const float* gx = g_Gx + (size_t)(t * 32 + bb) * K3_ + jbase + jl;
        float gxf = __ldg(gx);
        float gxo = __ldg(gx + 1024);
        float gxc = __ldg(gx + 2048);

        unsigned long long acc[4][3];
#pragma unroll
        for (int i = 0; i < 4; i++)
#pragma unroll
            for (int j = 0; j < 3; j++) acc[i][j] = pk2(0.f, 0.f);

        // ---- stage ALL of h (32768 floats) in one burst: 8 float4 per thread
        //      per 1/4, issued back-to-back for maximum MLP ----
        {
            const float4* src4 = (const float4*)g_hT[t & 1];
            float4* dst4 = (float4*)hs;
#pragma unroll
            for (int i = 0; i < 32; i++)
                dst4[tid + i * 256] = src4[tid + i * 256];
        }
        __syncthreads();

        // ---- GEMM over all 1024 k (k-split 8 ways across warps) ----
        const int kg0 = tk * 128;
#pragma unroll 4
        for (int kk = 0; kk < 128; kk++) {
            int kloc = kg0 + kk;
            float4 av = *(const float4*)&hs[kloc * 32 + tp * 4];
            unsigned long long aa[4];
            aa[0] = pk2(av.x, av.x); aa[1] = pk2(av.y, av.y);
            aa[2] = pk2(av.z, av.z); aa[3] = pk2(av.w, av.w);
            const unsigned long long* wp =
                (const unsigned long long*)&ws[kloc * NC_ + tc * 6];
            unsigned long long w0 = wp[0], w1 = wp[1], w2 = wp[2];
#pragma unroll
            for (int i = 0; i < 4; i++) {
                acc[i][0] = ffma2(aa[i], w0, acc[i][0]);
                acc[i][1] = ffma2(aa[i], w1, acc[i][1]);
                acc[i][2] = ffma2(aa[i], w2, acc[i][2]);
            }
        }
        __syncthreads();   // all GEMM reads of hs done — safe to reuse as gate

        // zero gate accumulators (aliases hs)
        for (int i = tid; i < NC_ * GPAD; i += 256) gate[i] = 0.f;
        __syncthreads();

        // reduce 8-way k-split partials into gate[cl][b]
#pragma unroll
        for (int i = 0; i < 4; i++) {
            int b = tp * 4 + i;
#pragma unroll
            for (int j = 0; j < 3; j++) {
                float2 v = up2(acc[i][j]);
                int cl = tc * 6 + j * 2;
                atomicAdd(&gate[cl * GPAD + b], v.x);
                atomicAdd(&gate[(cl + 1) * GPAD + b], v.y);
            }
        }
        __syncthreads();

        // ---- epilogue: gates -> cell update -> h ----
        {
            float sf = gate[jl * GPAD + bb]        + gxf;
            float so = gate[(8 + jl) * GPAD + bb]  + gxo;
            float sc = gate[(16 + jl) * GPAD + bb] + gxc;
            float f    = 1.f / (1.f + expf(-sf));
            float o    = 1.f / (1.f + expf(-so));
            float chat = tanhf(sc);
            float cn   = f * creg + (1.f - f) * chat;
            float hn   = o * tanhf(cn);
            creg = cn;
            out[(size_t)(bb * S_ + t) * H_ + jbase + jl] = hn;
            g_hT[1 - (t & 1)][(jbase + jl) * 32 + bb] = hn;
            if (t == S_ - 1) {
                out[(size_t)B_ * S_ * H_ + (size_t)bb * H_ + jbase + jl] = hn;  // h_T
                out[(size_t)B_ * S_ * H_ + (size_t)B_ * H_
                    + (size_t)bb * H_ + jbase + jl] = cn;                        // c_T
            }
        }

        // ---- grid barrier (R7: release fence+atomic; acquire nanosleep-poll) ----
        __threadfence();
        __syncthreads();
        if (tid == 0) {
            atomicAdd(&g_bar, 1u);
            unsigned target = (unsigned)GRID2 * (unsigned)(t + 1);
            while (*((volatile unsigned*)&g_bar) < target) __nanosleep(64);
            __threadfence();
        }
        __syncthreads();
    }
}

// ============================================================================
// Host launcher
// ============================================================================
extern "C" void kernel_launch(void* const* d_in, const int* in_sizes, int n_in,
                              void* d_out, int out_size) {
    (void)in_sizes; (void)n_in; (void)out_size;
    const float* x  = (const float*)d_in[0];
    const float* h0 = (const float*)d_in[1];
    const float* c0 = (const float*)d_in[2];
    const float* Wf = (const float*)d_in[3];
    const float* bf = (const float*)d_in[4];
    const float* Wo = (const float*)d_in[5];
    const float* bo = (const float*)d_in[6];
    const float* Wc = (const float*)d_in[7];
    const float* bc = (const float*)d_in[8];
    float* out = (float*)d_out;

    // 229376 B dynamic SMEM (96KB Wh + 128KB full h stage; gate aliases hs)
    // <= 232448 B block limit -> 1 CTA/SM, grid 128 <= SM count: co-resident.
    const int kSmem = (24576 + 32768) * 4;
    cudaFuncSetAttribute(lstm_kernel, cudaFuncAttributeMaxDynamicSharedMemorySize,
                         kSmem);

    dim3 g1(24, 256);
    xw_kernel<<<g1, 256>>>(x, h0, Wf, bf, Wo, bo, Wc, bc);

    lstm_kernel<<<GRID2, 256, kSmem>>>(Wf, Wo, Wc, c0, out);
}